// round 3
// baseline (speedup 1.0000x reference)
#include <cuda_runtime.h>
#include <cuda_bf16.h>
#include <stdint.h>

// Problem constants
#define DIM   256      // CODE_DIM
#define NC    1024     // SIZE (number of codes)
#define NPTS  65536    // N rows

// Tiling for the argmin kernel
#define BM    128      // rows per block
#define BN    128      // codes per tile
#define KC    128      // k-chunk staged for the w tile
#define TM    8        // rows per thread
#define TN    8        // codes per thread
// block = 16x16 = 256 threads; thread does TM x TN = 64 fp32 FMA lanes/k
// via 32 packed fma.rn.f32x2 (rows packed in pairs).

// Scratch (static device globals; no allocation)
__device__ int   g_idx[NPTS];
__device__ float g_wsq[NC];
__device__ float g_zsq[NPTS];

// ---- packed dual-fp32 helpers (IEEE rn per lane => bit-exact) -------------
static __device__ __forceinline__ unsigned long long pack2(float lo, float hi) {
    unsigned long long r;
    asm("mov.b64 %0, {%1, %2};" : "=l"(r) : "f"(lo), "f"(hi));
    return r;
}
static __device__ __forceinline__ void fma2(unsigned long long& d,
                                            unsigned long long a,
                                            unsigned long long b) {
    asm("fma.rn.f32x2 %0, %1, %2, %0;" : "+l"(d) : "l"(a), "l"(b));
}
static __device__ __forceinline__ void unpack2(unsigned long long v,
                                               float& lo, float& hi) {
    asm("mov.b64 {%0, %1}, %2;" : "=f"(lo), "=f"(hi) : "l"(v));
}

// ---------------------------------------------------------------------------
// Kernel 1: |w|^2 per code
// ---------------------------------------------------------------------------
__global__ void wsq_kernel(const float* __restrict__ w) {
    int c = blockIdx.x * blockDim.x + threadIdx.x;
    if (c >= NC) return;
    const float4* wr = reinterpret_cast<const float4*>(w + (size_t)c * DIM);
    float s = 0.f;
#pragma unroll 8
    for (int i = 0; i < DIM / 4; i++) {
        float4 v = wr[i];
        s += v.x * v.x + v.y * v.y + v.z * v.z + v.w * v.w;
    }
    g_wsq[c] = s;
}

// ---------------------------------------------------------------------------
// Kernel 1b: |z|^2 per row (warp per row, coalesced).
// Summation order is argmin-invariant: A shifts every code's distance by the
// same fp32 value (same binade => exact grid multiples).
// ---------------------------------------------------------------------------
__global__ void zsq_kernel(const float* __restrict__ z) {
    int warp = (blockIdx.x * blockDim.x + threadIdx.x) >> 5;
    int lane = threadIdx.x & 31;
    if (warp >= NPTS) return;
    const float4* zr = reinterpret_cast<const float4*>(z + (size_t)warp * DIM);
    float s = 0.f;
#pragma unroll
    for (int i = 0; i < 2; i++) {
        float4 v = zr[lane + 32 * i];
        s += v.x * v.x + v.y * v.y + v.z * v.z + v.w * v.w;
    }
#pragma unroll
    for (int m = 16; m >= 1; m >>= 1)
        s += __shfl_xor_sync(0xffffffffu, s, m);
    if (lane == 0) g_zsq[warp] = s;
}

// ---------------------------------------------------------------------------
// Kernel 2: per-row argmin over d = fl32( fl32(A - 2*B) + wsq ),
// emulating the reference's rounding (confirmed bit-exact in R2).
// Ties (common: d quantized to ~1.5e-5 grid) break to the LOWEST code index.
//
// smem: Az [DIM][BM] (full K, rows contiguous) = 128 KB
//       Bw [KC][BN]  (half-K chunk, codes contiguous) = 64 KB
// ---------------------------------------------------------------------------
__global__ void __launch_bounds__(256, 1)
argmin_kernel(const float* __restrict__ z, const float* __restrict__ w) {
    extern __shared__ float sm[];
    float* Az = sm;                 // [DIM][BM]
    float* Bw = sm + DIM * BM;      // [KC][BN]

    const int tid = threadIdx.x;
    const int tx  = tid & 15;       // code group
    const int ty  = tid >> 4;       // row group
    const int row0 = blockIdx.x * BM;

    // per-thread row |z|^2 values
    float Ar[TM];
#pragma unroll
    for (int r = 0; r < TM; r++) Ar[r] = g_zsq[row0 + ty * TM + r];

    // ---- stage z tile: 128 rows x 256 k, transposed into Az[k][row] ----
    for (int i = tid; i < (BM * DIM) / 4; i += 256) {
        int r  = i >> 6;            // i / (DIM/4)
        int kk = (i & 63) << 2;     // k offset
        float4 v = *reinterpret_cast<const float4*>(z + (size_t)(row0 + r) * DIM + kk);
        Az[(kk + 0) * BM + r] = v.x;
        Az[(kk + 1) * BM + r] = v.y;
        Az[(kk + 2) * BM + r] = v.z;
        Az[(kk + 3) * BM + r] = v.w;
    }

    float best[TM];
    int   bidx[TM];
#pragma unroll
    for (int r = 0; r < TM; r++) { best[r] = 3.4e38f; bidx[r] = 0x7fffffff; }

    for (int c0 = 0; c0 < NC; c0 += BN) {
        // packed accumulators: acc2[p][c] holds rows (2p, 2p+1) for code c
        unsigned long long acc2[TM / 2][TN];
#pragma unroll
        for (int p = 0; p < TM / 2; p++)
#pragma unroll
            for (int c = 0; c < TN; c++) acc2[p][c] = 0ull;

        for (int kc = 0; kc < DIM; kc += KC) {
            __syncthreads();  // protect Bw reuse (and Az on very first pass)
            // ---- stage w chunk: 128 codes x 128 k -> Bw[k_local][code] ----
            for (int i = tid; i < (BN * KC) / 4; i += 256) {
                int c  = i >> 5;            // i / (KC/4)
                int kk = (i & 31) << 2;
                float4 v = *reinterpret_cast<const float4*>(
                    w + (size_t)(c0 + c) * DIM + kc + kk);
                Bw[(kk + 0) * BN + c] = v.x;
                Bw[(kk + 1) * BN + c] = v.y;
                Bw[(kk + 2) * BN + c] = v.z;
                Bw[(kk + 3) * BN + c] = v.w;
            }
            __syncthreads();

#pragma unroll 4
            for (int kl = 0; kl < KC; kl++) {
                float4 b0 = *reinterpret_cast<float4*>(Bw + kl * BN + tx * TN);
                float4 b1 = *reinterpret_cast<float4*>(Bw + kl * BN + tx * TN + 4);
                float4 a0 = *reinterpret_cast<float4*>(Az + (kc + kl) * BM + ty * TM);
                float4 a1 = *reinterpret_cast<float4*>(Az + (kc + kl) * BM + ty * TM + 4);

                unsigned long long ap[TM / 2] = {
                    pack2(a0.x, a0.y), pack2(a0.z, a0.w),
                    pack2(a1.x, a1.y), pack2(a1.z, a1.w)
                };
                unsigned long long bp[TN] = {
                    pack2(b0.x, b0.x), pack2(b0.y, b0.y),
                    pack2(b0.z, b0.z), pack2(b0.w, b0.w),
                    pack2(b1.x, b1.x), pack2(b1.y, b1.y),
                    pack2(b1.z, b1.z), pack2(b1.w, b1.w)
                };
#pragma unroll
                for (int p = 0; p < TM / 2; p++)
#pragma unroll
                    for (int c = 0; c < TN; c++)
                        fma2(acc2[p][c], ap[p], bp[c]);
            }
        }

        // ---- fold this code tile into the running argmin ----
#pragma unroll
        for (int c = 0; c < TN; c++) {
            int code = c0 + tx * TN + c;
            float wsq = g_wsq[code];
#pragma unroll
            for (int p = 0; p < TM / 2; p++) {
                float blo, bhi;
                unpack2(acc2[p][c], blo, bhi);
                // emulate reference rounding: t = fl(A - 2B); d = fl(t + wsq)
                float t0 = __fsub_rn(Ar[2 * p + 0], __fmul_rn(2.0f, blo));
                float d0 = __fadd_rn(t0, wsq);
                float t1 = __fsub_rn(Ar[2 * p + 1], __fmul_rn(2.0f, bhi));
                float d1 = __fadd_rn(t1, wsq);
                // strict < keeps the earliest (lowest) code on exact ties,
                // since codes are visited in ascending order per thread
                if (d0 < best[2 * p + 0]) { best[2 * p + 0] = d0; bidx[2 * p + 0] = code; }
                if (d1 < best[2 * p + 1]) { best[2 * p + 1] = d1; bidx[2 * p + 1] = code; }
            }
        }
    }

    // ---- reduce across the 16 tx lanes (lexicographic on (d, idx)) ----
#pragma unroll
    for (int r = 0; r < TM; r++) {
        float v  = best[r];
        int   id = bidx[r];
#pragma unroll
        for (int m = 8; m >= 1; m >>= 1) {
            float ov = __shfl_xor_sync(0xffffffffu, v, m);
            int   oi = __shfl_xor_sync(0xffffffffu, id, m);
            if (ov < v || (ov == v && oi < id)) { v = ov; id = oi; }
        }
        if (tx == 0) g_idx[row0 + ty * TM + r] = id;
    }
}

// ---------------------------------------------------------------------------
// Kernel 3: gather quantized = weight[idx]  (float4 granularity)
// ---------------------------------------------------------------------------
__global__ void gather_kernel(const float* __restrict__ w, float* __restrict__ out) {
    long gid = (long)blockIdx.x * blockDim.x + threadIdx.x;  // over NPTS*64 float4
    if (gid >= (long)NPTS * (DIM / 4)) return;
    int row = (int)(gid >> 6);
    int col = (int)(gid & 63);
    const float4* w4 = reinterpret_cast<const float4*>(w);
    float4 v = w4[(size_t)g_idx[row] * (DIM / 4) + col];
    reinterpret_cast<float4*>(out)[gid] = v;
}

// ---------------------------------------------------------------------------
// Kernel 4: indices as FLOAT values (output dtype is float32), zero slack.
// ---------------------------------------------------------------------------
__global__ void idx_tail_kernel(float* __restrict__ out, int tail) {
    int i = blockIdx.x * blockDim.x + threadIdx.x;
    if (i >= tail) return;
    out[i] = (i < NPTS) ? (float)g_idx[i] : 0.0f;
}

__global__ void idx_only_kernel(float* __restrict__ out) {
    int i = blockIdx.x * blockDim.x + threadIdx.x;
    if (i < NPTS) out[i] = (float)g_idx[i];
}

// ---------------------------------------------------------------------------
extern "C" void kernel_launch(void* const* d_in, const int* in_sizes, int n_in,
                              void* d_out, int out_size) {
    const float* z = (const float*)d_in[0];   // [N, 256]
    const float* w = (const float*)d_in[1];   // [1024, 256]

    // norms
    wsq_kernel<<<(NC + 255) / 256, 256>>>(w);
    zsq_kernel<<<(NPTS * 32 + 255) / 256, 256>>>(z);

    // argmin (192 KB dynamic smem; attr set every call — idempotent)
    cudaFuncSetAttribute(argmin_kernel,
                         cudaFuncAttributeMaxDynamicSharedMemorySize,
                         (DIM * BM + KC * BN) * (int)sizeof(float));
    size_t smem = (size_t)(DIM * BM + KC * BN) * sizeof(float);
    argmin_kernel<<<NPTS / BM, 256, smem>>>(z, w);

    const long q_elems = (long)NPTS * DIM;

    if (out_size == NPTS) {
        // indices-only output (as float, per output dtype)
        idx_only_kernel<<<(NPTS + 255) / 256, 256>>>((float*)d_out);
    } else {
        // quantized block first
        long n4 = q_elems / 4;
        gather_kernel<<<(int)((n4 + 255) / 256), 256>>>(w, (float*)d_out);
        // tail = indices as float values, zero slack
        long tail = (long)out_size - q_elems;
        if (tail > 0) {
            idx_tail_kernel<<<(int)((tail + 255) / 256), 256>>>(
                (float*)d_out + q_elems, (int)tail);
        }
    }
}

// round 4
// speedup vs baseline: 1.4894x; 1.4894x over previous
#include <cuda_runtime.h>
#include <cuda_bf16.h>
#include <stdint.h>

// Problem constants
#define DIM   256      // CODE_DIM
#define NC    1024     // SIZE (number of codes)
#define NPTS  65536    // N rows
#define D4    (DIM/4)  // 64 float4 per row

// argmin tiling
#define THREADS 256
#define BM    64       // rows per CTA        (ty in [0,8), TM=8)
#define BN    128      // codes per tile      (tx in [0,32), TN=4, stride-32 interleaved)
#define TM    8
#define TN    4
#define KC    128      // k per Bw stage
#define KC4   (KC/4)   // 32 float4 columns
#define CHALF 512      // codes per CTA (half the codebook)
#define NTILE (CHALF/BN)  // 4 code tiles per CTA

// Scratch (static device globals; no allocation)
__device__ int   g_idx[NPTS];
__device__ float g_wsq[NC];
__device__ float g_zsq[NPTS];
__device__ float g_best2[2][NPTS];
__device__ int   g_bidx2[2][NPTS];

// ---- packed dual-fp32 helpers (IEEE rn per lane => exact per-lane fp32) ----
static __device__ __forceinline__ void fma2(unsigned long long& d,
                                            unsigned long long a,
                                            unsigned long long b) {
    asm("fma.rn.f32x2 %0, %1, %2, %0;" : "+l"(d) : "l"(a), "l"(b));
}
static __device__ __forceinline__ void unpack2(unsigned long long v,
                                               float& lo, float& hi) {
    asm("mov.b64 {%0, %1}, %2;" : "=f"(lo), "=f"(hi) : "l"(v));
}

// ---------------------------------------------------------------------------
// Kernel 1: |w|^2 per code
// ---------------------------------------------------------------------------
__global__ void wsq_kernel(const float* __restrict__ w) {
    int c = blockIdx.x * blockDim.x + threadIdx.x;
    if (c >= NC) return;
    const float4* wr = reinterpret_cast<const float4*>(w + (size_t)c * DIM);
    float s = 0.f;
#pragma unroll 8
    for (int i = 0; i < D4; i++) {
        float4 v = wr[i];
        s += v.x * v.x + v.y * v.y + v.z * v.z + v.w * v.w;
    }
    g_wsq[c] = s;
}

// ---------------------------------------------------------------------------
// Kernel 1b: |z|^2 per row (warp per row). Summation order is argmin-safe:
// A shifts every code's distance by the same fp32 value.
// ---------------------------------------------------------------------------
__global__ void zsq_kernel(const float* __restrict__ z) {
    int warp = (blockIdx.x * blockDim.x + threadIdx.x) >> 5;
    int lane = threadIdx.x & 31;
    if (warp >= NPTS) return;
    const float4* zr = reinterpret_cast<const float4*>(z + (size_t)warp * DIM);
    float s = 0.f;
#pragma unroll
    for (int i = 0; i < 2; i++) {
        float4 v = zr[lane + 32 * i];
        s += v.x * v.x + v.y * v.y + v.z * v.z + v.w * v.w;
    }
#pragma unroll
    for (int m = 16; m >= 1; m >>= 1)
        s += __shfl_xor_sync(0xffffffffu, s, m);
    if (lane == 0) g_zsq[warp] = s;
}

// ---------------------------------------------------------------------------
// Kernel 2: partial argmin over one codebook half.
// d = fl32( fl32(A - 2*B) + wsq )  (reference rounding; confirmed bit-exact).
// Dot-product orientation: acc2[r][c] accumulates (even-k, odd-k) fp32 pair
// via fma.rn.f32x2 with both operands loaded as natural 64-bit k-pairs.
//
// smem: Az [BM][D4]   float4, k-contiguous (plain copy)        = 64 KB
//       Bw [BN][KC4]  float4, column q stored at (q ^ (c&31))  = 64 KB
// ---------------------------------------------------------------------------
__global__ void __launch_bounds__(THREADS, 1)
argmin_kernel(const float4* __restrict__ z4, const float4* __restrict__ w4) {
    extern __shared__ float4 sm4[];
    float4* Az = sm4;             // [BM][D4]
    float4* Bw = sm4 + BM * D4;   // [BN][KC4], swizzled columns

    const int tid  = threadIdx.x;
    const int tx   = tid & 31;    // code lane
    const int ty   = tid >> 5;    // row group (warp id), 0..7
    const int bx   = blockIdx.x;
    const int half = bx & 1;
    const int row0 = (bx >> 1) * BM;
    const int cbase = half * CHALF;

    // ---- stage z block (pure coalesced copy, no transpose) ----
    for (int i = tid; i < BM * D4; i += THREADS)
        Az[i] = z4[(size_t)(row0 + (i >> 6)) * D4 + (i & 63)];

    float Ar[TM];
#pragma unroll
    for (int r = 0; r < TM; r++) Ar[r] = g_zsq[row0 + ty * TM + r];

    float best[TM];
    int   bidx[TM];
#pragma unroll
    for (int r = 0; r < TM; r++) { best[r] = 3.4e38f; bidx[r] = 0x7fffffff; }

    for (int t = 0; t < NTILE; t++) {
        const int c0 = cbase + t * BN;

        unsigned long long acc[TM][TN];
#pragma unroll
        for (int r = 0; r < TM; r++)
#pragma unroll
            for (int c = 0; c < TN; c++) acc[r][c] = 0ull;

        for (int kc4 = 0; kc4 < D4; kc4 += KC4) {
            __syncthreads();  // previous tile's compute done / Bw reusable
            // ---- stage w tile: coalesced LDG, swizzled column STS ----
            for (int i = tid; i < BN * KC4; i += THREADS) {
                int c = i >> 5;          // code row 0..127
                int q = i & 31;          // float4 column
                Bw[c * KC4 + (q ^ (c & 31))] =
                    w4[(size_t)(c0 + c) * D4 + kc4 + q];
            }
            __syncthreads();

#pragma unroll 2
            for (int q = 0; q < KC4; q++) {
                ulonglong2 a[TM];
#pragma unroll
                for (int r = 0; r < TM; r++)
                    a[r] = *reinterpret_cast<const ulonglong2*>(
                        &Az[(ty * TM + r) * D4 + kc4 + q]);
#pragma unroll
                for (int c = 0; c < TN; c++) {
                    ulonglong2 b = *reinterpret_cast<const ulonglong2*>(
                        &Bw[(c * 32 + tx) * KC4 + (q ^ tx)]);
#pragma unroll
                    for (int r = 0; r < TM; r++) {
                        fma2(acc[r][c], a[r].x, b.x);
                        fma2(acc[r][c], a[r].y, b.y);
                    }
                }
            }
        }

        // ---- fold tile into running argmin (codes ascending per thread) ----
#pragma unroll
        for (int c = 0; c < TN; c++) {
            int code = c0 + c * 32 + tx;
            float wsq = g_wsq[code];
#pragma unroll
            for (int r = 0; r < TM; r++) {
                float blo, bhi;
                unpack2(acc[r][c], blo, bhi);
                float B = __fadd_rn(blo, bhi);
                // reference rounding: t = fl(A - 2B); d = fl(t + wsq)
                float tt = __fsub_rn(Ar[r], __fmul_rn(2.0f, B));
                float d  = __fadd_rn(tt, wsq);
                if (d < best[r]) { best[r] = d; bidx[r] = code; }
            }
        }
    }

    // ---- full-warp lexicographic argmin reduce over the 32 code lanes ----
#pragma unroll
    for (int r = 0; r < TM; r++) {
        float v  = best[r];
        int   id = bidx[r];
#pragma unroll
        for (int m = 16; m >= 1; m >>= 1) {
            float ov = __shfl_xor_sync(0xffffffffu, v, m);
            int   oi = __shfl_xor_sync(0xffffffffu, id, m);
            if (ov < v || (ov == v && oi < id)) { v = ov; id = oi; }
        }
        if (tx == 0) {
            g_best2[half][row0 + ty * TM + r] = v;
            g_bidx2[half][row0 + ty * TM + r] = id;
        }
    }
}

// ---------------------------------------------------------------------------
// Kernel 2b: merge the two half-codebook partials (lexicographic on (d,idx))
// ---------------------------------------------------------------------------
__global__ void merge_kernel() {
    int i = blockIdx.x * blockDim.x + threadIdx.x;
    if (i >= NPTS) return;
    float v0 = g_best2[0][i], v1 = g_best2[1][i];
    int   i0 = g_bidx2[0][i], i1 = g_bidx2[1][i];
    g_idx[i] = (v1 < v0 || (v1 == v0 && i1 < i0)) ? i1 : i0;
}

// ---------------------------------------------------------------------------
// Kernel 3: gather quantized = weight[idx]
// ---------------------------------------------------------------------------
__global__ void gather_kernel(const float* __restrict__ w, float* __restrict__ out) {
    long gid = (long)blockIdx.x * blockDim.x + threadIdx.x;
    if (gid >= (long)NPTS * D4) return;
    int row = (int)(gid >> 6);
    int col = (int)(gid & 63);
    const float4* w4 = reinterpret_cast<const float4*>(w);
    reinterpret_cast<float4*>(out)[gid] = w4[(size_t)g_idx[row] * D4 + col];
}

// ---------------------------------------------------------------------------
// Kernel 4: indices as FLOAT values (output dtype float32), zero slack
// ---------------------------------------------------------------------------
__global__ void idx_tail_kernel(float* __restrict__ out, int tail) {
    int i = blockIdx.x * blockDim.x + threadIdx.x;
    if (i >= tail) return;
    out[i] = (i < NPTS) ? (float)g_idx[i] : 0.0f;
}

__global__ void idx_only_kernel(float* __restrict__ out) {
    int i = blockIdx.x * blockDim.x + threadIdx.x;
    if (i < NPTS) out[i] = (float)g_idx[i];
}

// ---------------------------------------------------------------------------
extern "C" void kernel_launch(void* const* d_in, const int* in_sizes, int n_in,
                              void* d_out, int out_size) {
    const float* z = (const float*)d_in[0];   // [N, 256]
    const float* w = (const float*)d_in[1];   // [1024, 256]

    // norms
    wsq_kernel<<<(NC + 255) / 256, 256>>>(w);
    zsq_kernel<<<(NPTS * 32 + 255) / 256, 256>>>(z);

    // partial argmin over 2 codebook halves x 1024 row blocks
    cudaFuncSetAttribute(argmin_kernel,
                         cudaFuncAttributeMaxDynamicSharedMemorySize,
                         (BM * D4 + BN * KC4) * (int)sizeof(float4));
    size_t smem = (size_t)(BM * D4 + BN * KC4) * sizeof(float4);
    argmin_kernel<<<(NPTS / BM) * 2, THREADS, smem>>>(
        reinterpret_cast<const float4*>(z), reinterpret_cast<const float4*>(w));

    merge_kernel<<<(NPTS + 255) / 256, 256>>>();

    const long q_elems = (long)NPTS * DIM;

    if (out_size == NPTS) {
        idx_only_kernel<<<(NPTS + 255) / 256, 256>>>((float*)d_out);
    } else {
        long n4 = q_elems / 4;
        gather_kernel<<<(int)((n4 + 255) / 256), 256>>>(w, (float*)d_out);
        long tail = (long)out_size - q_elems;
        if (tail > 0) {
            idx_tail_kernel<<<(int)((tail + 255) / 256), 256>>>(
                (float*)d_out + q_elems, (int)tail);
        }
    }
}

// round 7
// speedup vs baseline: 2.4947x; 1.6750x over previous
#include <cuda_runtime.h>
#include <cuda_bf16.h>
#include <stdint.h>

// Problem constants
#define DIM   256
#define NC    1024
#define NPTS  65536
#define D4    (DIM/4)

// ---- filter kernel geometry ----
#define ROWS_CTA 64
#define NCT      8          // code tiles of 128
#define KC       64
#define THR      256        // 8 warps: wy=wid>>2 (M), wx=wid&3 (N)
#define NSTAGE   32
#define TAU      1.25e-4f

// filter smem offsets
#define SM_WSQ   0                     // 4 KB
#define SM_RED   4096                  // 4 KB: v1,i1,v2,i2 [64][4]
#define SM_A     8192                  // 2 splits x 4 kc x 64 r x 128 B = 64 KB
#define SM_B     (SM_A + 65536)        // 2 bufs x 2 splits x 128 r x 128 B = 64 KB
#define SM_TOTAL (SM_B + 65536)        // 139264 B

// ---- resolver geometry (R4 clone, indirect rows) ----
#define RBM   64
#define RBN   128
#define RKC4  32
#define RTM   8
#define RTN   4
#define RCHALF 512
#define RNTILE (RCHALF/RBN)
#define RSM_TOTAL (65536 + 65536 + 256)

// Scratch (static device globals; no allocation)
__device__ int   g_idx[NPTS];
__device__ float g_wsq[NC];
__device__ float g_zsq[NPTS];
__device__ int   g_ambig_n;
__device__ int   g_ambig[NPTS];
__device__ float g_best2[2][NPTS];
__device__ int   g_bidx2[2][NPTS];
__device__ __align__(16) unsigned short g_zh[NPTS * DIM];
__device__ __align__(16) unsigned short g_zm[NPTS * DIM];
__device__ __align__(16) unsigned short g_wh[NC * DIM];
__device__ __align__(16) unsigned short g_wm[NC * DIM];

// ---- PTX helpers (baseline ops only; no arch-'a' features) -----------------
static __device__ __forceinline__ uint32_t smem_u32(const void* p) {
    uint32_t a;
    asm("{ .reg .u64 t; cvta.to.shared.u64 t, %1; cvt.u32.u64 %0, t; }"
        : "=r"(a) : "l"(p));
    return a;
}
#define CP16(dst, src) \
    asm volatile("cp.async.cg.shared.global [%0], [%1], 16;" :: "r"(dst), "l"(src))
#define LDSM4(r, addr) \
    asm volatile("ldmatrix.sync.aligned.m8n8.x4.shared.b16 {%0,%1,%2,%3}, [%4];" \
                 : "=r"((r)[0]), "=r"((r)[1]), "=r"((r)[2]), "=r"((r)[3]) : "r"(addr))
#define MMA16816(d, a, b) \
    asm volatile("mma.sync.aligned.m16n8k16.row.col.f32.bf16.bf16.f32 " \
                 "{%0,%1,%2,%3}, {%4,%5,%6,%7}, {%8,%9}, {%0,%1,%2,%3};" \
                 : "+f"((d)[0]), "+f"((d)[1]), "+f"((d)[2]), "+f"((d)[3]) \
                 : "r"((a)[0]), "r"((a)[1]), "r"((a)[2]), "r"((a)[3]), \
                   "r"((b)[0]), "r"((b)[1]))
static __device__ __forceinline__ void fma2(unsigned long long& d,
                                            unsigned long long a,
                                            unsigned long long b) {
    asm("fma.rn.f32x2 %0, %1, %2, %0;" : "+l"(d) : "l"(a), "l"(b));
}
static __device__ __forceinline__ void unpack2(unsigned long long v,
                                               float& lo, float& hi) {
    asm("mov.b64 {%0, %1}, %2;" : "=f"(lo), "=f"(hi) : "l"(v));
}

// 2-way Dekker split: x = h + m + r, |r| <= 2^-16 |x| (h,m exact residual)
static __device__ __forceinline__ void split2(float x, unsigned short& h,
                                              unsigned short& m) {
    __nv_bfloat16 bh = __float2bfloat16_rn(x);
    float r1 = x - __bfloat162float(bh);   // exact
    __nv_bfloat16 bm = __float2bfloat16_rn(r1);
    h = __bfloat16_as_ushort(bh);
    m = __bfloat16_as_ushort(bm);
}

// ---------------------------------------------------------------------------
// [1] split w -> (wh, wm), |w|^2; reset worklist counter
// ---------------------------------------------------------------------------
__global__ void split_w_kernel(const float* __restrict__ w) {
    if (blockIdx.x == 0 && threadIdx.x == 0) g_ambig_n = 0;
    int row  = (blockIdx.x * blockDim.x + threadIdx.x) >> 5;
    int lane = threadIdx.x & 31;
    if (row >= NC) return;
    const float4* src = reinterpret_cast<const float4*>(w + (size_t)row * DIM);
    float s = 0.f;
#pragma unroll
    for (int i = 0; i < 2; i++) {
        float4 v = src[lane + 32 * i];
        float x[4] = {v.x, v.y, v.z, v.w};
        unsigned short h[4], m[4];
#pragma unroll
        for (int j = 0; j < 4; j++) { split2(x[j], h[j], m[j]); s += x[j] * x[j]; }
        size_t o = (size_t)row * D4 + lane + 32 * i;
        reinterpret_cast<ushort4*>(g_wh)[o] = make_ushort4(h[0], h[1], h[2], h[3]);
        reinterpret_cast<ushort4*>(g_wm)[o] = make_ushort4(m[0], m[1], m[2], m[3]);
    }
#pragma unroll
    for (int t = 16; t >= 1; t >>= 1) s += __shfl_xor_sync(0xffffffffu, s, t);
    if (lane == 0) g_wsq[row] = s;
}

// ---------------------------------------------------------------------------
// [2] split z -> (zh, zm)
// ---------------------------------------------------------------------------
__global__ void split_z_kernel(const float* __restrict__ z) {
    int row  = (blockIdx.x * blockDim.x + threadIdx.x) >> 5;
    int lane = threadIdx.x & 31;
    if (row >= NPTS) return;
    const float4* src = reinterpret_cast<const float4*>(z + (size_t)row * DIM);
#pragma unroll
    for (int i = 0; i < 2; i++) {
        float4 v = src[lane + 32 * i];
        float x[4] = {v.x, v.y, v.z, v.w};
        unsigned short h[4], m[4];
#pragma unroll
        for (int j = 0; j < 4; j++) split2(x[j], h[j], m[j]);
        size_t o = (size_t)row * D4 + lane + 32 * i;
        reinterpret_cast<ushort4*>(g_zh)[o] = make_ushort4(h[0], h[1], h[2], h[3]);
        reinterpret_cast<ushort4*>(g_zm)[o] = make_ushort4(m[0], m[1], m[2], m[3]);
    }
}

// ---------------------------------------------------------------------------
// [3] |z|^2 per row
// ---------------------------------------------------------------------------
__global__ void zsq_kernel(const float* __restrict__ z) {
    int row  = (blockIdx.x * blockDim.x + threadIdx.x) >> 5;
    int lane = threadIdx.x & 31;
    if (row >= NPTS) return;
    const float4* zr = reinterpret_cast<const float4*>(z + (size_t)row * DIM);
    float s = 0.f;
#pragma unroll
    for (int i = 0; i < 2; i++) {
        float4 v = zr[lane + 32 * i];
        s += v.x * v.x + v.y * v.y + v.z * v.z + v.w * v.w;
    }
#pragma unroll
    for (int t = 16; t >= 1; t >>= 1) s += __shfl_xor_sync(0xffffffffu, s, t);
    if (lane == 0) g_zsq[row] = s;
}

// ---------------------------------------------------------------------------
// B chunk stage: 2 splits x 128 codes x 64 k (32 KB)
// ---------------------------------------------------------------------------
static __device__ __forceinline__ void stage_B_chunk(uint32_t sb, int tid, int it) {
    const unsigned short* const ws[2] = {g_wh, g_wm};
    const int ct = it >> 2, kc = it & 3, buf = it & 1;
#pragma unroll
    for (int i = tid; i < 2048; i += THR) {
        int s   = i >> 10;
        int rem = i & 1023;
        int r = rem >> 3, q = rem & 7;
        const unsigned short* src = ws[s] + ((size_t)(ct * 128 + r) * DIM + kc * KC + q * 8);
        uint32_t off = (uint32_t)(r * 128 + ((q * 16) ^ ((r & 7) << 4)));
        CP16(sb + SM_B + buf * 32768 + s * 16384 + off, src);
    }
}

// lex insert of candidate (v,i) into best-2
static __device__ __forceinline__ void ins2(float v, int i, float& b1v, int& b1i,
                                            float& b2v, int& b2i) {
    if (v < b1v || (v == b1v && i < b1i)) { b2v = b1v; b2i = b1i; b1v = v; b1i = i; }
    else if (v < b2v || (v == b2v && i < b2i)) { b2v = v; b2i = i; }
}

// ---------------------------------------------------------------------------
// [4] HOT: bf16x2-split HMMA filter + best-2 + margin test
// ---------------------------------------------------------------------------
__global__ void __launch_bounds__(THR, 1)
mma_filter_kernel() {
    extern __shared__ char smem[];
    const uint32_t sb = smem_u32(smem);
    const int tid  = threadIdx.x;
    const int lane = tid & 31;
    const int wid  = tid >> 5;
    const int wx   = wid & 3;
    const int wy   = wid >> 2;
    const int row0 = blockIdx.x * ROWS_CTA;

    float* swsq = reinterpret_cast<float*>(smem + SM_WSQ);
    for (int i = tid; i < NC; i += THR) swsq[i] = g_wsq[i];

    // stage A (full K, 2 splits)
    {
        const unsigned short* const zs[2] = {g_zh, g_zm};
#pragma unroll
        for (int i = tid; i < 4096; i += THR) {
            int s    = i >> 11;
            int rem  = i & 2047;
            int kc   = rem >> 9;
            int rem2 = rem & 511;
            int r = rem2 >> 3, q = rem2 & 7;
            const unsigned short* src = zs[s] + ((size_t)(row0 + r) * DIM + kc * KC + q * 8);
            uint32_t off = (uint32_t)(r * 128 + ((q * 16) ^ ((r & 7) << 4)));
            CP16(sb + SM_A + (s * 4 + kc) * 8192 + off, src);
        }
    }
    stage_B_chunk(sb, tid, 0);
    asm volatile("cp.async.commit_group;" ::: "memory");

    float Azr[2][2];
#pragma unroll
    for (int mt = 0; mt < 2; mt++)
#pragma unroll
        for (int g = 0; g < 2; g++)
            Azr[mt][g] = g_zsq[row0 + wy * 32 + mt * 16 + (lane >> 2) + g * 8];

    float b1v[2][2], b2v[2][2];
    int   b1i[2][2], b2i[2][2];
#pragma unroll
    for (int mt = 0; mt < 2; mt++)
#pragma unroll
        for (int g = 0; g < 2; g++) {
            b1v[mt][g] = b2v[mt][g] = 3.4e38f;
            b1i[mt][g] = b2i[mt][g] = 0x7fffffff;
        }

    const uint32_t xl   = (uint32_t)((lane & 7) << 4);
    const uint32_t aRow = (uint32_t)((wy * 32 + (lane & 15)) * 128);
    const uint32_t akh  = (uint32_t)(((lane >> 4) & 1) * 16);
    const uint32_t bRow = (uint32_t)((wx * 32 + ((lane >> 4) << 3) + (lane & 7)) * 128);
    const uint32_t bkh  = (uint32_t)(((lane >> 3) & 1) * 16);

    const int pa[3] = {0, 0, 1};
    const int pb[3] = {0, 1, 0};

    for (int ct = 0; ct < NCT; ct++) {
        float acc[2][4][4];
#pragma unroll
        for (int mt = 0; mt < 2; mt++)
#pragma unroll
            for (int nt = 0; nt < 4; nt++)
#pragma unroll
                for (int e = 0; e < 4; e++) acc[mt][nt][e] = 0.f;

        for (int kc = 0; kc < 4; kc++) {
            const int it = ct * 4 + kc;
            if (it + 1 < NSTAGE) {
                stage_B_chunk(sb, tid, it + 1);
                asm volatile("cp.async.commit_group;" ::: "memory");
                asm volatile("cp.async.wait_group 1;" ::: "memory");
            } else {
                asm volatile("cp.async.wait_group 0;" ::: "memory");
            }
            __syncthreads();

            const uint32_t ab = sb + SM_A + kc * 8192;         // + s*32768
            const uint32_t bb = sb + SM_B + (it & 1) * 32768;  // + s*16384

#pragma unroll
            for (int k16 = 0; k16 < 4; k16++) {
                uint32_t af[2][2][4], bf[2][2][4];
                const uint32_t ak = ((uint32_t)(k16 * 32) + akh) ^ xl;
                const uint32_t bk = ((uint32_t)(k16 * 32) + bkh) ^ xl;
#pragma unroll
                for (int s = 0; s < 2; s++) {
#pragma unroll
                    for (int mt = 0; mt < 2; mt++)
                        LDSM4(af[s][mt], ab + s * 32768 + aRow + mt * 2048 + ak);
#pragma unroll
                    for (int pr = 0; pr < 2; pr++)
                        LDSM4(bf[s][pr], bb + s * 16384 + bRow + pr * 2048 + bk);
                }
#pragma unroll
                for (int p = 0; p < 3; p++)
#pragma unroll
                    for (int mt = 0; mt < 2; mt++)
#pragma unroll
                        for (int nt = 0; nt < 4; nt++)
                            MMA16816(acc[mt][nt], af[pa[p]][mt],
                                     &bf[pb[p]][nt >> 1][(nt & 1) * 2]);
            }
            __syncthreads();
        }

        // fold tile into best-2 (codes ascend per thread)
#pragma unroll
        for (int nt = 0; nt < 4; nt++) {
            int code0 = ct * 128 + wx * 32 + nt * 8 + (lane & 3) * 2;
            float w0 = swsq[code0], w1 = swsq[code0 + 1];
#pragma unroll
            for (int mt = 0; mt < 2; mt++)
#pragma unroll
                for (int g = 0; g < 2; g++) {
                    float B0 = acc[mt][nt][g * 2 + 0];
                    float B1 = acc[mt][nt][g * 2 + 1];
                    float d0 = __fadd_rn(__fsub_rn(Azr[mt][g], __fmul_rn(2.f, B0)), w0);
                    float d1 = __fadd_rn(__fsub_rn(Azr[mt][g], __fmul_rn(2.f, B1)), w1);
                    ins2(d0, code0,     b1v[mt][g], b1i[mt][g], b2v[mt][g], b2i[mt][g]);
                    ins2(d1, code0 + 1, b1v[mt][g], b1i[mt][g], b2v[mt][g], b2i[mt][g]);
                }
        }
    }

    // reduce best-2 across the 4 code-lanes (xor 1,2 touch only lane&3)
    float* rv1 = reinterpret_cast<float*>(smem + SM_RED);
    int*   ri1 = reinterpret_cast<int*>(smem + SM_RED + 1024);
    float* rv2 = reinterpret_cast<float*>(smem + SM_RED + 2048);
    int*   ri2 = reinterpret_cast<int*>(smem + SM_RED + 3072);
#pragma unroll
    for (int mt = 0; mt < 2; mt++)
#pragma unroll
        for (int g = 0; g < 2; g++) {
            float v1 = b1v[mt][g], v2 = b2v[mt][g];
            int   i1 = b1i[mt][g], i2 = b2i[mt][g];
#pragma unroll
            for (int m = 1; m <= 2; m <<= 1) {
                float o1v = __shfl_xor_sync(0xffffffffu, v1, m);
                int   o1i = __shfl_xor_sync(0xffffffffu, i1, m);
                float o2v = __shfl_xor_sync(0xffffffffu, v2, m);
                int   o2i = __shfl_xor_sync(0xffffffffu, i2, m);
                ins2(o1v, o1i, v1, i1, v2, i2);
                ins2(o2v, o2i, v1, i1, v2, i2);
            }
            if ((lane & 3) == 0) {
                int rl = wy * 32 + mt * 16 + (lane >> 2) + g * 8;
                rv1[rl * 4 + wx] = v1; ri1[rl * 4 + wx] = i1;
                rv2[rl * 4 + wx] = v2; ri2[rl * 4 + wx] = i2;
            }
        }
    __syncthreads();

    if (tid < ROWS_CTA) {
        float v1 = rv1[tid * 4], v2 = rv2[tid * 4];
        int   i1 = ri1[tid * 4], i2 = ri2[tid * 4];
#pragma unroll
        for (int j = 1; j < 4; j++) {
            ins2(rv1[tid * 4 + j], ri1[tid * 4 + j], v1, i1, v2, i2);
            ins2(rv2[tid * 4 + j], ri2[tid * 4 + j], v1, i1, v2, i2);
        }
        int row = row0 + tid;
        g_idx[row] = i1;
        if (!(v2 - v1 > TAU)) {          // ambiguous -> exact resolve
            int p = atomicAdd(&g_ambig_n, 1);
            g_ambig[p] = row;
        }
    }
}

// ---------------------------------------------------------------------------
// [5] resolver: exact fp32 rescan (R4 semantics) of ambiguous rows, indirect.
// ---------------------------------------------------------------------------
__global__ void __launch_bounds__(256, 1)
resolve_kernel(const float4* __restrict__ z4, const float4* __restrict__ w4) {
    extern __shared__ float4 sm4[];
    float4* Az = sm4;                    // [RBM][D4]
    float4* Bw = sm4 + RBM * D4;         // [RBN][RKC4] swizzled
    int* rmap  = reinterpret_cast<int*>(sm4 + RBM * D4 + RBN * RKC4);

    const int cnt = g_ambig_n;
    const int bx  = blockIdx.x;
    const int slot0 = (bx >> 1) * RBM;
    if (slot0 >= cnt) return;
    const int half  = bx & 1;
    const int cbase = half * RCHALF;

    const int tid = threadIdx.x;
    const int tx  = tid & 31;
    const int ty  = tid >> 5;

    if (tid < RBM) {
        int s = slot0 + tid;
        rmap[tid] = g_ambig[s < cnt ? s : cnt - 1];
    }
    __syncthreads();

    for (int i = tid; i < RBM * D4; i += 256)
        Az[i] = z4[(size_t)rmap[i >> 6] * D4 + (i & 63)];

    float Ar[RTM];
#pragma unroll
    for (int r = 0; r < RTM; r++) Ar[r] = g_zsq[rmap[ty * RTM + r]];

    float best[RTM];
    int   bidx[RTM];
#pragma unroll
    for (int r = 0; r < RTM; r++) { best[r] = 3.4e38f; bidx[r] = 0x7fffffff; }

    for (int t = 0; t < RNTILE; t++) {
        const int c0 = cbase + t * RBN;

        unsigned long long acc[RTM][RTN];
#pragma unroll
        for (int r = 0; r < RTM; r++)
#pragma unroll
            for (int c = 0; c < RTN; c++) acc[r][c] = 0ull;

        for (int kc4 = 0; kc4 < D4; kc4 += RKC4) {
            __syncthreads();
            for (int i = tid; i < RBN * RKC4; i += 256) {
                int c = i >> 5, q = i & 31;
                Bw[c * RKC4 + (q ^ (c & 31))] = w4[(size_t)(c0 + c) * D4 + kc4 + q];
            }
            __syncthreads();

#pragma unroll 2
            for (int q = 0; q < RKC4; q++) {
                ulonglong2 a[RTM];
#pragma unroll
                for (int r = 0; r < RTM; r++)
                    a[r] = *reinterpret_cast<const ulonglong2*>(
                        &Az[(ty * RTM + r) * D4 + kc4 + q]);
#pragma unroll
                for (int c = 0; c < RTN; c++) {
                    ulonglong2 b = *reinterpret_cast<const ulonglong2*>(
                        &Bw[(c * 32 + tx) * RKC4 + (q ^ tx)]);
#pragma unroll
                    for (int r = 0; r < RTM; r++) {
                        fma2(acc[r][c], a[r].x, b.x);
                        fma2(acc[r][c], a[r].y, b.y);
                    }
                }
            }
        }

#pragma unroll
        for (int c = 0; c < RTN; c++) {
            int code = c0 + c * 32 + tx;
            float wsq = g_wsq[code];
#pragma unroll
            for (int r = 0; r < RTM; r++) {
                float blo, bhi;
                unpack2(acc[r][c], blo, bhi);
                float B = __fadd_rn(blo, bhi);
                float tt = __fsub_rn(Ar[r], __fmul_rn(2.0f, B));
                float d  = __fadd_rn(tt, wsq);
                if (d < best[r]) { best[r] = d; bidx[r] = code; }
            }
        }
    }

#pragma unroll
    for (int r = 0; r < RTM; r++) {
        float v  = best[r];
        int   id = bidx[r];
#pragma unroll
        for (int m = 16; m >= 1; m >>= 1) {
            float ov = __shfl_xor_sync(0xffffffffu, v, m);
            int   oi = __shfl_xor_sync(0xffffffffu, id, m);
            if (ov < v || (ov == v && oi < id)) { v = ov; id = oi; }
        }
        if (tx == 0 && slot0 + ty * RTM + r < cnt) {
            int row = rmap[ty * RTM + r];
            g_best2[half][row] = v;
            g_bidx2[half][row] = id;
        }
    }
}

// ---------------------------------------------------------------------------
// [6] merge resolver halves for ambiguous rows
// ---------------------------------------------------------------------------
__global__ void rmerge_kernel() {
    int i = blockIdx.x * blockDim.x + threadIdx.x;
    if (i >= g_ambig_n) return;
    int row = g_ambig[i];
    float v0 = g_best2[0][row], v1 = g_best2[1][row];
    int   i0 = g_bidx2[0][row], i1 = g_bidx2[1][row];
    g_idx[row] = (v1 < v0 || (v1 == v0 && i1 < i0)) ? i1 : i0;
}

// ---------------------------------------------------------------------------
// [7] gather, [8] index tail
// ---------------------------------------------------------------------------
__global__ void gather_kernel(const float* __restrict__ w, float* __restrict__ out) {
    long gid = (long)blockIdx.x * blockDim.x + threadIdx.x;
    if (gid >= (long)NPTS * D4) return;
    int row = (int)(gid >> 6);
    int col = (int)(gid & 63);
    const float4* w4 = reinterpret_cast<const float4*>(w);
    reinterpret_cast<float4*>(out)[gid] = w4[(size_t)g_idx[row] * D4 + col];
}

__global__ void idx_tail_kernel(float* __restrict__ out, int tail) {
    int i = blockIdx.x * blockDim.x + threadIdx.x;
    if (i >= tail) return;
    out[i] = (i < NPTS) ? (float)g_idx[i] : 0.0f;
}

__global__ void idx_only_kernel(float* __restrict__ out) {
    int i = blockIdx.x * blockDim.x + threadIdx.x;
    if (i < NPTS) out[i] = (float)g_idx[i];
}

// ---------------------------------------------------------------------------
extern "C" void kernel_launch(void* const* d_in, const int* in_sizes, int n_in,
                              void* d_out, int out_size) {
    const float* z = (const float*)d_in[0];
    const float* w = (const float*)d_in[1];

    split_w_kernel<<<(NC * 32 + 255) / 256, 256>>>(w);           // [1]
    split_z_kernel<<<(NPTS * 32 + 255) / 256, 256>>>(z);         // [2]
    zsq_kernel<<<(NPTS * 32 + 255) / 256, 256>>>(z);             // [3]

    cudaFuncSetAttribute(mma_filter_kernel,
                         cudaFuncAttributeMaxDynamicSharedMemorySize, SM_TOTAL);
    mma_filter_kernel<<<NPTS / ROWS_CTA, THR, SM_TOTAL>>>();     // [4] HOT

    cudaFuncSetAttribute(resolve_kernel,
                         cudaFuncAttributeMaxDynamicSharedMemorySize, RSM_TOTAL);
    resolve_kernel<<<(NPTS / RBM) * 2, 256, RSM_TOTAL>>>(        // [5]
        reinterpret_cast<const float4*>(z), reinterpret_cast<const float4*>(w));

    rmerge_kernel<<<NPTS / 256, 256>>>();                        // [6]

    const long q_elems = (long)NPTS * DIM;
    if (out_size == NPTS) {
        idx_only_kernel<<<(NPTS + 255) / 256, 256>>>((float*)d_out);
    } else {
        long n4 = q_elems / 4;
        gather_kernel<<<(int)((n4 + 255) / 256), 256>>>(w, (float*)d_out);  // [7]
        long tail = (long)out_size - q_elems;
        if (tail > 0) {
            idx_tail_kernel<<<(int)((tail + 255) / 256), 256>>>(
                (float*)d_out + q_elems, (int)tail);                         // [8]
        }
    }
}

// round 8
// speedup vs baseline: 2.8853x; 1.1566x over previous
#include <cuda_runtime.h>
#include <cuda_bf16.h>
#include <stdint.h>

// Problem constants
#define DIM   256
#define NC    1024
#define NPTS  65536
#define D4    (DIM/4)

// ---- filter kernel geometry ----
#define ROWS_CTA 128
#define NCT      8          // code tiles of 128
#define KC       64
#define THR      512        // 16 warps: wy=wid>>2 (M, 32 rows), wx=wid&3 (N, 32 codes)
#define NSTAGE   32
#define TAU      1.25e-4f

// filter smem offsets
#define SM_WSQ   0                     // 4 KB
#define SM_RED   4096                  // 8 KB: rv1,ri1,rv2,ri2 [128][4]
#define SM_A     12288                 // 2 splits x 4 kc x 128 r x 128 B = 128 KB
#define SM_B     (SM_A + 131072)       // 2 bufs x 2 splits x 128 r x 128 B = 64 KB
#define SM_TOTAL (SM_B + 65536)        // 208896 B

// ---- resolver geometry (proven-exact fp32 rescan, indirect rows) ----
#define RBM   64
#define RBN   128
#define RKC4  32
#define RTM   8
#define RTN   4
#define RCHALF 512
#define RNTILE (RCHALF/RBN)
#define RSM_TOTAL (65536 + 65536 + 256)

// Scratch (static device globals; no allocation)
__device__ int   g_idx[NPTS];
__device__ float g_wsq[NC];
__device__ float g_zsq[NPTS];
__device__ int   g_ambig_n;
__device__ int   g_ambig[NPTS];
__device__ float g_best2[2][NPTS];
__device__ int   g_bidx2[2][NPTS];
__device__ __align__(16) unsigned short g_zh[NPTS * DIM];
__device__ __align__(16) unsigned short g_zm[NPTS * DIM];
__device__ __align__(16) unsigned short g_wh[NC * DIM];
__device__ __align__(16) unsigned short g_wm[NC * DIM];

// ---- PTX helpers (baseline ops only; no arch-'a' features) -----------------
static __device__ __forceinline__ uint32_t smem_u32(const void* p) {
    uint32_t a;
    asm("{ .reg .u64 t; cvta.to.shared.u64 t, %1; cvt.u32.u64 %0, t; }"
        : "=r"(a) : "l"(p));
    return a;
}
#define CP16(dst, src) \
    asm volatile("cp.async.cg.shared.global [%0], [%1], 16;" :: "r"(dst), "l"(src))
#define LDSM4(r, addr) \
    asm volatile("ldmatrix.sync.aligned.m8n8.x4.shared.b16 {%0,%1,%2,%3}, [%4];" \
                 : "=r"((r)[0]), "=r"((r)[1]), "=r"((r)[2]), "=r"((r)[3]) : "r"(addr))
#define MMA16816(d, a, b) \
    asm volatile("mma.sync.aligned.m16n8k16.row.col.f32.bf16.bf16.f32 " \
                 "{%0,%1,%2,%3}, {%4,%5,%6,%7}, {%8,%9}, {%0,%1,%2,%3};" \
                 : "+f"((d)[0]), "+f"((d)[1]), "+f"((d)[2]), "+f"((d)[3]) \
                 : "r"((a)[0]), "r"((a)[1]), "r"((a)[2]), "r"((a)[3]), \
                   "r"((b)[0]), "r"((b)[1]))
static __device__ __forceinline__ void fma2(unsigned long long& d,
                                            unsigned long long a,
                                            unsigned long long b) {
    asm("fma.rn.f32x2 %0, %1, %2, %0;" : "+l"(d) : "l"(a), "l"(b));
}
static __device__ __forceinline__ void unpack2(unsigned long long v,
                                               float& lo, float& hi) {
    asm("mov.b64 {%0, %1}, %2;" : "=f"(lo), "=f"(hi) : "l"(v));
}

// 2-way Dekker split: x = h + m + r, |r| <= 2^-17 |x| (residuals exact)
static __device__ __forceinline__ void split2(float x, unsigned short& h,
                                              unsigned short& m) {
    __nv_bfloat16 bh = __float2bfloat16_rn(x);
    float r1 = x - __bfloat162float(bh);   // exact
    __nv_bfloat16 bm = __float2bfloat16_rn(r1);
    h = __bfloat16_as_ushort(bh);
    m = __bfloat16_as_ushort(bm);
}

// ---------------------------------------------------------------------------
// [0] reset worklist counter
// ---------------------------------------------------------------------------
__global__ void reset_kernel() { g_ambig_n = 0; }

// ---------------------------------------------------------------------------
// [1] split w -> (wh, wm) + |w|^2
// ---------------------------------------------------------------------------
__global__ void split_w_kernel(const float* __restrict__ w) {
    int row  = (blockIdx.x * blockDim.x + threadIdx.x) >> 5;
    int lane = threadIdx.x & 31;
    if (row >= NC) return;
    const float4* src = reinterpret_cast<const float4*>(w + (size_t)row * DIM);
    float s = 0.f;
#pragma unroll
    for (int i = 0; i < 2; i++) {
        float4 v = src[lane + 32 * i];
        float x[4] = {v.x, v.y, v.z, v.w};
        unsigned short h[4], m[4];
#pragma unroll
        for (int j = 0; j < 4; j++) { split2(x[j], h[j], m[j]); s += x[j] * x[j]; }
        size_t o = (size_t)row * D4 + lane + 32 * i;
        reinterpret_cast<ushort4*>(g_wh)[o] = make_ushort4(h[0], h[1], h[2], h[3]);
        reinterpret_cast<ushort4*>(g_wm)[o] = make_ushort4(m[0], m[1], m[2], m[3]);
    }
#pragma unroll
    for (int t = 16; t >= 1; t >>= 1) s += __shfl_xor_sync(0xffffffffu, s, t);
    if (lane == 0) g_wsq[row] = s;
}

// ---------------------------------------------------------------------------
// [2] split z -> (zh, zm) + |z|^2 (fused: z read once)
// ---------------------------------------------------------------------------
__global__ void split_z_kernel(const float* __restrict__ z) {
    int row  = (blockIdx.x * blockDim.x + threadIdx.x) >> 5;
    int lane = threadIdx.x & 31;
    if (row >= NPTS) return;
    const float4* src = reinterpret_cast<const float4*>(z + (size_t)row * DIM);
    float s = 0.f;
#pragma unroll
    for (int i = 0; i < 2; i++) {
        float4 v = src[lane + 32 * i];
        float x[4] = {v.x, v.y, v.z, v.w};
        unsigned short h[4], m[4];
#pragma unroll
        for (int j = 0; j < 4; j++) { split2(x[j], h[j], m[j]); s += x[j] * x[j]; }
        size_t o = (size_t)row * D4 + lane + 32 * i;
        reinterpret_cast<ushort4*>(g_zh)[o] = make_ushort4(h[0], h[1], h[2], h[3]);
        reinterpret_cast<ushort4*>(g_zm)[o] = make_ushort4(m[0], m[1], m[2], m[3]);
    }
#pragma unroll
    for (int t = 16; t >= 1; t >>= 1) s += __shfl_xor_sync(0xffffffffu, s, t);
    if (lane == 0) g_zsq[row] = s;
}

// ---------------------------------------------------------------------------
// B chunk stage: 2 splits x 128 codes x 64 k (32 KB)
// ---------------------------------------------------------------------------
static __device__ __forceinline__ void stage_B_chunk(uint32_t sb, int tid, int it) {
    const unsigned short* const ws[2] = {g_wh, g_wm};
    const int ct = it >> 2, kc = it & 3, buf = it & 1;
#pragma unroll
    for (int i = tid; i < 2048; i += THR) {
        int s   = i >> 10;
        int rem = i & 1023;
        int r = rem >> 3, q = rem & 7;
        const unsigned short* src = ws[s] + ((size_t)(ct * 128 + r) * DIM + kc * KC + q * 8);
        uint32_t off = (uint32_t)(r * 128 + ((q * 16) ^ ((r & 7) << 4)));
        CP16(sb + SM_B + buf * 32768 + s * 16384 + off, src);
    }
}

// lex insert of candidate (v,i) into best-2
static __device__ __forceinline__ void ins2(float v, int i, float& b1v, int& b1i,
                                            float& b2v, int& b2i) {
    if (v < b1v || (v == b1v && i < b1i)) { b2v = b1v; b2i = b1i; b1v = v; b1i = i; }
    else if (v < b2v || (v == b2v && i < b2i)) { b2v = v; b2i = i; }
}

// ---------------------------------------------------------------------------
// [3] HOT: bf16x2-split HMMA filter + best-2 + margin test.
// 512 threads, 16 warps (4 M x 4 N), 128 rows x 1024 codes per CTA.
// ---------------------------------------------------------------------------
__global__ void __launch_bounds__(THR, 1)
mma_filter_kernel() {
    extern __shared__ char smem[];
    const uint32_t sb = smem_u32(smem);
    const int tid  = threadIdx.x;
    const int lane = tid & 31;
    const int wid  = tid >> 5;
    const int wx   = wid & 3;        // N warp (32 codes)
    const int wy   = wid >> 2;       // M warp (32 rows)
    const int row0 = blockIdx.x * ROWS_CTA;

    float* swsq = reinterpret_cast<float*>(smem + SM_WSQ);
    for (int i = tid; i < NC; i += THR) swsq[i] = g_wsq[i];

    // stage A (full K, 2 splits): block (s,kc) at SM_A + s*65536 + kc*16384
    {
        const unsigned short* const zs[2] = {g_zh, g_zm};
#pragma unroll
        for (int i = tid; i < 8192; i += THR) {
            int s    = i >> 12;
            int rem  = i & 4095;
            int kc   = rem >> 10;
            int rem2 = rem & 1023;
            int r = rem2 >> 3, q = rem2 & 7;
            const unsigned short* src = zs[s] + ((size_t)(row0 + r) * DIM + kc * KC + q * 8);
            uint32_t off = (uint32_t)(r * 128 + ((q * 16) ^ ((r & 7) << 4)));
            CP16(sb + SM_A + s * 65536 + kc * 16384 + off, src);
        }
    }
    stage_B_chunk(sb, tid, 0);
    asm volatile("cp.async.commit_group;" ::: "memory");

    float Azr[2][2];
#pragma unroll
    for (int mt = 0; mt < 2; mt++)
#pragma unroll
        for (int g = 0; g < 2; g++)
            Azr[mt][g] = g_zsq[row0 + wy * 32 + mt * 16 + (lane >> 2) + g * 8];

    float b1v[2][2], b2v[2][2];
    int   b1i[2][2], b2i[2][2];
#pragma unroll
    for (int mt = 0; mt < 2; mt++)
#pragma unroll
        for (int g = 0; g < 2; g++) {
            b1v[mt][g] = b2v[mt][g] = 3.4e38f;
            b1i[mt][g] = b2i[mt][g] = 0x7fffffff;
        }

    const uint32_t xl   = (uint32_t)((lane & 7) << 4);
    const uint32_t aRow = (uint32_t)((wy * 32 + (lane & 15)) * 128);
    const uint32_t akh  = (uint32_t)(((lane >> 4) & 1) * 16);
    const uint32_t bRow = (uint32_t)((wx * 32 + ((lane >> 4) << 3) + (lane & 7)) * 128);
    const uint32_t bkh  = (uint32_t)(((lane >> 3) & 1) * 16);

    const int pa[3] = {0, 0, 1};
    const int pb[3] = {0, 1, 0};

    for (int ct = 0; ct < NCT; ct++) {
        float acc[2][4][4];
#pragma unroll
        for (int mt = 0; mt < 2; mt++)
#pragma unroll
            for (int nt = 0; nt < 4; nt++)
#pragma unroll
                for (int e = 0; e < 4; e++) acc[mt][nt][e] = 0.f;

        for (int kc = 0; kc < 4; kc++) {
            const int it = ct * 4 + kc;
            if (it + 1 < NSTAGE) {
                stage_B_chunk(sb, tid, it + 1);
                asm volatile("cp.async.commit_group;" ::: "memory");
                asm volatile("cp.async.wait_group 1;" ::: "memory");
            } else {
                asm volatile("cp.async.wait_group 0;" ::: "memory");
            }
            __syncthreads();

            const uint32_t ab = sb + SM_A + kc * 16384;        // + s*65536
            const uint32_t bb = sb + SM_B + (it & 1) * 32768;  // + s*16384

#pragma unroll
            for (int k16 = 0; k16 < 4; k16++) {
                uint32_t af[2][2][4], bf[2][2][4];
                const uint32_t ak = ((uint32_t)(k16 * 32) + akh) ^ xl;
                const uint32_t bk = ((uint32_t)(k16 * 32) + bkh) ^ xl;
#pragma unroll
                for (int s = 0; s < 2; s++) {
#pragma unroll
                    for (int mt = 0; mt < 2; mt++)
                        LDSM4(af[s][mt], ab + s * 65536 + aRow + mt * 2048 + ak);
#pragma unroll
                    for (int pr = 0; pr < 2; pr++)
                        LDSM4(bf[s][pr], bb + s * 16384 + bRow + pr * 2048 + bk);
                }
#pragma unroll
                for (int p = 0; p < 3; p++)
#pragma unroll
                    for (int mt = 0; mt < 2; mt++)
#pragma unroll
                        for (int nt = 0; nt < 4; nt++)
                            MMA16816(acc[mt][nt], af[pa[p]][mt],
                                     &bf[pb[p]][nt >> 1][(nt & 1) * 2]);
            }
            __syncthreads();
        }

        // fold tile into best-2 (codes ascend per thread)
#pragma unroll
        for (int nt = 0; nt < 4; nt++) {
            int code0 = ct * 128 + wx * 32 + nt * 8 + (lane & 3) * 2;
            float w0 = swsq[code0], w1 = swsq[code0 + 1];
#pragma unroll
            for (int mt = 0; mt < 2; mt++)
#pragma unroll
                for (int g = 0; g < 2; g++) {
                    float B0 = acc[mt][nt][g * 2 + 0];
                    float B1 = acc[mt][nt][g * 2 + 1];
                    float d0 = __fadd_rn(__fsub_rn(Azr[mt][g], __fmul_rn(2.f, B0)), w0);
                    float d1 = __fadd_rn(__fsub_rn(Azr[mt][g], __fmul_rn(2.f, B1)), w1);
                    ins2(d0, code0,     b1v[mt][g], b1i[mt][g], b2v[mt][g], b2i[mt][g]);
                    ins2(d1, code0 + 1, b1v[mt][g], b1i[mt][g], b2v[mt][g], b2i[mt][g]);
                }
        }
    }

    // reduce best-2 across the 4 code-lanes (xor 1,2 stay within lane&3 group)
    float* rv1 = reinterpret_cast<float*>(smem + SM_RED);
    int*   ri1 = reinterpret_cast<int*>(smem + SM_RED + 2048);
    float* rv2 = reinterpret_cast<float*>(smem + SM_RED + 4096);
    int*   ri2 = reinterpret_cast<int*>(smem + SM_RED + 6144);
#pragma unroll
    for (int mt = 0; mt < 2; mt++)
#pragma unroll
        for (int g = 0; g < 2; g++) {
            float v1 = b1v[mt][g], v2 = b2v[mt][g];
            int   i1 = b1i[mt][g], i2 = b2i[mt][g];
#pragma unroll
            for (int m = 1; m <= 2; m <<= 1) {
                float o1v = __shfl_xor_sync(0xffffffffu, v1, m);
                int   o1i = __shfl_xor_sync(0xffffffffu, i1, m);
                float o2v = __shfl_xor_sync(0xffffffffu, v2, m);
                int   o2i = __shfl_xor_sync(0xffffffffu, i2, m);
                ins2(o1v, o1i, v1, i1, v2, i2);
                ins2(o2v, o2i, v1, i1, v2, i2);
            }
            if ((lane & 3) == 0) {
                int rl = wy * 32 + mt * 16 + (lane >> 2) + g * 8;
                rv1[rl * 4 + wx] = v1; ri1[rl * 4 + wx] = i1;
                rv2[rl * 4 + wx] = v2; ri2[rl * 4 + wx] = i2;
            }
        }
    __syncthreads();

    if (tid < ROWS_CTA) {
        float v1 = rv1[tid * 4], v2 = rv2[tid * 4];
        int   i1 = ri1[tid * 4], i2 = ri2[tid * 4];
#pragma unroll
        for (int j = 1; j < 4; j++) {
            ins2(rv1[tid * 4 + j], ri1[tid * 4 + j], v1, i1, v2, i2);
            ins2(rv2[tid * 4 + j], ri2[tid * 4 + j], v1, i1, v2, i2);
        }
        int row = row0 + tid;
        g_idx[row] = i1;
        if (!(v2 - v1 > TAU)) {          // ambiguous -> exact resolve
            int p = atomicAdd(&g_ambig_n, 1);
            g_ambig[p] = row;
        }
    }
}

// ---------------------------------------------------------------------------
// [4] resolver: exact fp32 rescan (proven semantics) of ambiguous rows.
// ---------------------------------------------------------------------------
__global__ void __launch_bounds__(256, 1)
resolve_kernel(const float4* __restrict__ z4, const float4* __restrict__ w4) {
    extern __shared__ float4 sm4[];
    float4* Az = sm4;                    // [RBM][D4]
    float4* Bw = sm4 + RBM * D4;         // [RBN][RKC4] swizzled
    int* rmap  = reinterpret_cast<int*>(sm4 + RBM * D4 + RBN * RKC4);

    const int cnt = g_ambig_n;
    const int bx  = blockIdx.x;
    const int slot0 = (bx >> 1) * RBM;
    if (slot0 >= cnt) return;
    const int half  = bx & 1;
    const int cbase = half * RCHALF;

    const int tid = threadIdx.x;
    const int tx  = tid & 31;
    const int ty  = tid >> 5;

    if (tid < RBM) {
        int s = slot0 + tid;
        rmap[tid] = g_ambig[s < cnt ? s : cnt - 1];
    }
    __syncthreads();

    for (int i = tid; i < RBM * D4; i += 256)
        Az[i] = z4[(size_t)rmap[i >> 6] * D4 + (i & 63)];

    float Ar[RTM];
#pragma unroll
    for (int r = 0; r < RTM; r++) Ar[r] = g_zsq[rmap[ty * RTM + r]];

    float best[RTM];
    int   bidx[RTM];
#pragma unroll
    for (int r = 0; r < RTM; r++) { best[r] = 3.4e38f; bidx[r] = 0x7fffffff; }

    for (int t = 0; t < RNTILE; t++) {
        const int c0 = cbase + t * RBN;

        unsigned long long acc[RTM][RTN];
#pragma unroll
        for (int r = 0; r < RTM; r++)
#pragma unroll
            for (int c = 0; c < RTN; c++) acc[r][c] = 0ull;

        for (int kc4 = 0; kc4 < D4; kc4 += RKC4) {
            __syncthreads();
            for (int i = tid; i < RBN * RKC4; i += 256) {
                int c = i >> 5, q = i & 31;
                Bw[c * RKC4 + (q ^ (c & 31))] = w4[(size_t)(c0 + c) * D4 + kc4 + q];
            }
            __syncthreads();

#pragma unroll 2
            for (int q = 0; q < RKC4; q++) {
                ulonglong2 a[RTM];
#pragma unroll
                for (int r = 0; r < RTM; r++)
                    a[r] = *reinterpret_cast<const ulonglong2*>(
                        &Az[(ty * RTM + r) * D4 + kc4 + q]);
#pragma unroll
                for (int c = 0; c < RTN; c++) {
                    ulonglong2 b = *reinterpret_cast<const ulonglong2*>(
                        &Bw[(c * 32 + tx) * RKC4 + (q ^ tx)]);
#pragma unroll
                    for (int r = 0; r < RTM; r++) {
                        fma2(acc[r][c], a[r].x, b.x);
                        fma2(acc[r][c], a[r].y, b.y);
                    }
                }
            }
        }

#pragma unroll
        for (int c = 0; c < RTN; c++) {
            int code = c0 + c * 32 + tx;
            float wsq = g_wsq[code];
#pragma unroll
            for (int r = 0; r < RTM; r++) {
                float blo, bhi;
                unpack2(acc[r][c], blo, bhi);
                float B = __fadd_rn(blo, bhi);
                float tt = __fsub_rn(Ar[r], __fmul_rn(2.0f, B));
                float d  = __fadd_rn(tt, wsq);
                if (d < best[r]) { best[r] = d; bidx[r] = code; }
            }
        }
    }

#pragma unroll
    for (int r = 0; r < RTM; r++) {
        float v  = best[r];
        int   id = bidx[r];
#pragma unroll
        for (int m = 16; m >= 1; m >>= 1) {
            float ov = __shfl_xor_sync(0xffffffffu, v, m);
            int   oi = __shfl_xor_sync(0xffffffffu, id, m);
            if (ov < v || (ov == v && oi < id)) { v = ov; id = oi; }
        }
        if (tx == 0 && slot0 + ty * RTM + r < cnt) {
            int row = rmap[ty * RTM + r];
            g_best2[half][row] = v;
            g_bidx2[half][row] = id;
        }
    }
}

// ---------------------------------------------------------------------------
// [5] merge resolver halves for ambiguous rows
// ---------------------------------------------------------------------------
__global__ void rmerge_kernel() {
    int i = blockIdx.x * blockDim.x + threadIdx.x;
    if (i >= g_ambig_n) return;
    int row = g_ambig[i];
    float v0 = g_best2[0][row], v1 = g_best2[1][row];
    int   i0 = g_bidx2[0][row], i1 = g_bidx2[1][row];
    g_idx[row] = (v1 < v0 || (v1 == v0 && i1 < i0)) ? i1 : i0;
}

// ---------------------------------------------------------------------------
// [6] gather, [7] index tail
// ---------------------------------------------------------------------------
__global__ void gather_kernel(const float* __restrict__ w, float* __restrict__ out) {
    long gid = (long)blockIdx.x * blockDim.x + threadIdx.x;
    if (gid >= (long)NPTS * D4) return;
    int row = (int)(gid >> 6);
    int col = (int)(gid & 63);
    const float4* w4 = reinterpret_cast<const float4*>(w);
    reinterpret_cast<float4*>(out)[gid] = w4[(size_t)g_idx[row] * D4 + col];
}

__global__ void idx_tail_kernel(float* __restrict__ out, int tail) {
    int i = blockIdx.x * blockDim.x + threadIdx.x;
    if (i >= tail) return;
    out[i] = (i < NPTS) ? (float)g_idx[i] : 0.0f;
}

__global__ void idx_only_kernel(float* __restrict__ out) {
    int i = blockIdx.x * blockDim.x + threadIdx.x;
    if (i < NPTS) out[i] = (float)g_idx[i];
}

// ---------------------------------------------------------------------------
extern "C" void kernel_launch(void* const* d_in, const int* in_sizes, int n_in,
                              void* d_out, int out_size) {
    const float* z = (const float*)d_in[0];
    const float* w = (const float*)d_in[1];

    reset_kernel<<<1, 1>>>();                                    // [0]
    split_w_kernel<<<(NC * 32 + 255) / 256, 256>>>(w);           // [1]
    split_z_kernel<<<(NPTS * 32 + 255) / 256, 256>>>(z);         // [2]

    cudaFuncSetAttribute(mma_filter_kernel,
                         cudaFuncAttributeMaxDynamicSharedMemorySize, SM_TOTAL);
    mma_filter_kernel<<<NPTS / ROWS_CTA, THR, SM_TOTAL>>>();     // [3] HOT

    cudaFuncSetAttribute(resolve_kernel,
                         cudaFuncAttributeMaxDynamicSharedMemorySize, RSM_TOTAL);
    resolve_kernel<<<(NPTS / RBM) * 2, 256, RSM_TOTAL>>>(        // [4]
        reinterpret_cast<const float4*>(z), reinterpret_cast<const float4*>(w));

    rmerge_kernel<<<NPTS / 256, 256>>>();                        // [5]

    const long q_elems = (long)NPTS * DIM;
    if (out_size == NPTS) {
        idx_only_kernel<<<(NPTS + 255) / 256, 256>>>((float*)d_out);
    } else {
        long n4 = q_elems / 4;
        gather_kernel<<<(int)((n4 + 255) / 256), 256>>>(w, (float*)d_out);  // [6]
        long tail = (long)out_size - q_elems;
        if (tail > 0) {
            idx_tail_kernel<<<(int)((tail + 255) / 256), 256>>>(
                (float*)d_out + q_elems, (int)tail);                         // [7]
        }
    }
}